// round 4
// baseline (speedup 1.0000x reference)
#include <cuda_runtime.h>

// Shape fixed by setup_inputs: x [8, 8192, 512] fp32, weight [512] fp32.
#define BB 8
#define TT 8192
#define CC 512
#define EPSF 1e-5f

#define THREADS 256              // 8 warps
#define FPB 32                   // frames per block (one per lane in scan)
#define BPB (TT / FPB)           // 256 blocks per batch
#define GRID (BB * BPB)          // 2048 blocks
#define FPW (FPB / (THREADS/32)) // 4 frames per warp

// Double-buffered published aggregates: low 32b = value, high 32b = flag.
// Statics are zero-initialized, so parity 0 starts clean.
__device__ unsigned long long g_pubS1[2][GRID];
__device__ unsigned long long g_pubD[2][GRID];
__device__ int g_parity;
__device__ unsigned int g_done;

__device__ __forceinline__ void publish(unsigned long long* slot, float v) {
    *(volatile unsigned long long*)slot =
        (1ull << 32) | (unsigned long long)__float_as_uint(v);
}

// Sum predecessor aggregates (indices [0, kb) of this batch), spinning on flags.
// Warp-collective over warp 0.
__device__ __forceinline__ float lookback(unsigned long long* base, int kb, int lane) {
    float v = 0.f;
    for (int idx = lane; idx < kb; idx += 32) {
        unsigned long long u;
        do {
            u = *(volatile unsigned long long*)&base[idx];
        } while (!(u >> 32));
        v += __uint_as_float((unsigned)u);
    }
#pragma unroll
    for (int o = 16; o > 0; o >>= 1) v += __shfl_xor_sync(0xffffffffu, v, o);
    return v;
}

__global__ void __launch_bounds__(THREADS, 2)
fused(const float* __restrict__ x, const float* __restrict__ w,
      float* __restrict__ out) {
    __shared__ float sS1[FPB];
    __shared__ float sQ[FPB];
    __shared__ float sMean[FPB];
    __shared__ float sInv[FPB];
    __shared__ float sW[CC];

    const int p = *(volatile int*)&g_parity;
    const int b = blockIdx.x / BPB;
    const int kb = blockIdx.x % BPB;
    const int wid = threadIdx.x >> 5;
    const int lane = threadIdx.x & 31;
    const size_t frame0 = (size_t)b * TT + (size_t)kb * FPB;

    // Clear the other parity's slots for the NEXT launch (safe: this launch
    // only ever reads parity p).
    if (threadIdx.x == 0) {
        *(volatile unsigned long long*)&g_pubS1[1 - p][blockIdx.x] = 0ull;
        *(volatile unsigned long long*)&g_pubD[1 - p][blockIdx.x] = 0ull;
    }

    // Weight -> shared (512 floats).
    for (int i = threadIdx.x; i < CC; i += THREADS) sW[i] = w[i];

    // ---------------- Phase 1: load x into registers, per-frame reduce -----
    // Warp `wid` owns frames [wid*4, wid*4+4). Lane holds 16 floats per frame.
    float4 xv[FPW][4];
#pragma unroll
    for (int j = 0; j < FPW; j++) {
        const float4* px =
            reinterpret_cast<const float4*>(x + (frame0 + wid * FPW + j) * CC);
#pragma unroll
        for (int k = 0; k < 4; k++) xv[j][k] = px[lane + k * 32];
    }
#pragma unroll
    for (int j = 0; j < FPW; j++) {
        float s = 0.f, q = 0.f;
#pragma unroll
        for (int k = 0; k < 4; k++) {
            float4 v = xv[j][k];
            s += (v.x + v.y) + (v.z + v.w);
            q += v.x * v.x + v.y * v.y + v.z * v.z + v.w * v.w;
        }
#pragma unroll
        for (int o = 16; o > 0; o >>= 1) {
            s += __shfl_xor_sync(0xffffffffu, s, o);
            q += __shfl_xor_sync(0xffffffffu, q, o);
        }
        if (lane == 0) { sS1[wid * FPW + j] = s; sQ[wid * FPW + j] = q; }
    }
    __syncthreads();

    // ---------------- Warp 0: scans + lookbacks + stats --------------------
    if (wid == 0) {
        const float s1 = sS1[lane];
        const float q = sQ[lane];

        // Inclusive warp scan of S1 (one frame per lane).
        float incl = s1;
#pragma unroll
        for (int o = 1; o < 32; o <<= 1) {
            float t = __shfl_up_sync(0xffffffffu, incl, o);
            if (lane >= o) incl += t;
        }
        if (lane == 31) publish(&g_pubS1[p][blockIdx.x], incl);
        const float excl1 = lookback(&g_pubS1[p][b * BPB], kb, lane);

        const int t = kb * FPB + lane;
        const float cnt = (float)(t + 1) * (float)CC;
        const float m = (excl1 + incl) / cnt;
        sMean[lane] = m;

        // D = sum_c (x - m)^2 for this frame, then scan.
        float D = q - 2.f * m * s1 + (float)CC * m * m;
        float inclD = D;
#pragma unroll
        for (int o = 1; o < 32; o <<= 1) {
            float tt = __shfl_up_sync(0xffffffffu, inclD, o);
            if (lane >= o) inclD += tt;
        }
        if (lane == 31) publish(&g_pubD[p][blockIdx.x], inclD);
        const float exclD = lookback(&g_pubD[p][b * BPB], kb, lane);

        const float var = (exclD + inclD) / cnt;
        sInv[lane] = rsqrtf(var + EPSF);
    }
    __syncthreads();

    // ---------------- Phase 3: normalize straight from registers -----------
    const float4* w4 = reinterpret_cast<const float4*>(sW);
#pragma unroll
    for (int j = 0; j < FPW; j++) {
        const int f = wid * FPW + j;
        const float m = sMean[f];
        const float iv = sInv[f];
        float4* po = reinterpret_cast<float4*>(out + (frame0 + f) * CC);
#pragma unroll
        for (int k = 0; k < 4; k++) {
            float4 v = xv[j][k];
            float4 wv = w4[lane + k * 32];
            float4 r;
            r.x = (v.x - m) * iv * wv.x;
            r.y = (v.y - m) * iv * wv.y;
            r.z = (v.z - m) * iv * wv.z;
            r.w = (v.w - m) * iv * wv.w;
            __stcs(&po[lane + k * 32], r);
        }
    }

    // ---------------- Epilogue: last block flips parity for next launch ----
    __syncthreads();
    if (threadIdx.x == 0) {
        __threadfence();
        unsigned int n = atomicAdd(&g_done, 1u);
        if (n == GRID - 1) {
            g_done = 0;
            g_parity = p ^ 1;
        }
    }
}

extern "C" void kernel_launch(void* const* d_in, const int* in_sizes, int n_in,
                              void* d_out, int out_size) {
    const float* x = (const float*)d_in[0];
    const float* w = (const float*)d_in[1];
    float* out = (float*)d_out;
    fused<<<GRID, THREADS>>>(x, w, out);
}